// round 4
// baseline (speedup 1.0000x reference)
#include <cuda_runtime.h>
#include <cstdint>

#define NB   2
#define SEQ  2048
#define DM   1024
#define NH   16
#define DHD  64

// Scratch (allocation-free rule: __device__ globals)
static __device__ float g_Q[NB*NH*SEQ*DHD];
static __device__ float g_K[NB*NH*SEQ*DHD];
static __device__ float g_V[NB*NH*SEQ*DHD];
static __device__ float g_Z[(size_t)NB*SEQ*DM];

__device__ __forceinline__ float to_tf32(float x){
    float y; asm("cvt.rna.tf32.f32 %0, %1;" : "=f"(y) : "f"(x)); return y;
}
__device__ __forceinline__ float4 tf4(float4 v){
    return make_float4(to_tf32(v.x), to_tf32(v.y), to_tf32(v.z), to_tf32(v.w));
}
__device__ __forceinline__ unsigned fu(float x){ return __float_as_uint(x); }
__device__ __forceinline__ float fast_ex2(float x){
    float y; asm("ex2.approx.f32 %0, %1;" : "=f"(y) : "f"(x)); return y;
}
__device__ __forceinline__ void mma8(float* c,
    unsigned a0, unsigned a1, unsigned a2, unsigned a3,
    unsigned b0, unsigned b1)
{
    asm volatile(
      "mma.sync.aligned.m16n8k8.row.col.f32.tf32.tf32.f32 "
      "{%0,%1,%2,%3},{%4,%5,%6,%7},{%8,%9},{%0,%1,%2,%3};"
      : "+f"(c[0]), "+f"(c[1]), "+f"(c[2]), "+f"(c[3])
      : "r"(a0), "r"(a1), "r"(a2), "r"(a3), "r"(b0), "r"(b1));
}

// ---------------------------------------------------------------------------
// Kernel 1: QKV projection.  C[4096, 1024-cols-per-matrix] tiles of 128x128.
// grid (32, 8, 3): x=row tile, y=col tile (2 heads), z in {Q,K,V}.
// Output layout: [b][h][s][e]  (per-(b,h) contiguous for attention).
// ---------------------------------------------------------------------------
__global__ __launch_bounds__(256) void qkv_kernel(
    const float* __restrict__ x,
    const float* __restrict__ Wq, const float* __restrict__ Wk, const float* __restrict__ Wv,
    const float* __restrict__ bq, const float* __restrict__ bk, const float* __restrict__ bv)
{
    __shared__ float As[128][20];   // 128 rows x 16 k (+4 pad) -> frag reads conflict-free
    __shared__ float Bs[16][136];   // 16 k x 128 cols (+8 pad) -> frag reads conflict-free

    const int tid  = threadIdx.x;
    const int warp = tid >> 5, lane = tid & 31;
    const int g = lane >> 2, tg = lane & 3;
    const int wm = warp >> 1, wn = warp & 1;
    const int row0 = blockIdx.x * 128;
    const int col0 = blockIdx.y * 128;
    const int z = blockIdx.z;

    const float* W    = (z == 0) ? Wq : (z == 1) ? Wk : Wv;
    const float* bias = (z == 0) ? bq : (z == 1) ? bk : bv;
    float* Out        = (z == 0) ? g_Q : (z == 1) ? g_K : g_V;

    float acc[2][8][4];
    #pragma unroll
    for (int i = 0; i < 2; i++)
        #pragma unroll
        for (int j = 0; j < 8; j++)
            #pragma unroll
            for (int k = 0; k < 4; k++) acc[i][j][k] = 0.f;

    for (int k0 = 0; k0 < DM; k0 += 16) {
        __syncthreads();
        // A tile: 128x16 = 512 float4, 2 per thread
        #pragma unroll
        for (int u = 0; u < 2; u++) {
            int i = tid + u * 256;
            int r = i >> 2, q = i & 3;
            float4 v = *(const float4*)(x + (size_t)(row0 + r) * DM + k0 + q * 4);
            *(float4*)&As[r][q * 4] = tf4(v);
        }
        // B tile: 16x128 = 512 float4 (tile spans exactly 2 heads)
        #pragma unroll
        for (int u = 0; u < 2; u++) {
            int i = tid + u * 256;
            int k = i >> 5, cq = i & 31;
            int cg = col0 + cq * 4;
            int h = cg >> 6, e = cg & 63;
            float4 v = *(const float4*)(W + ((size_t)h * DM + k0 + k) * DHD + e);
            *(float4*)&Bs[k][cq * 4] = tf4(v);
        }
        __syncthreads();

        #pragma unroll
        for (int ks = 0; ks < 2; ks++) {
            unsigned a[2][4];
            #pragma unroll
            for (int mt = 0; mt < 2; mt++) {
                int r = wm * 32 + mt * 16 + g;
                a[mt][0] = fu(As[r    ][ks * 8 + tg]);
                a[mt][1] = fu(As[r + 8][ks * 8 + tg]);
                a[mt][2] = fu(As[r    ][ks * 8 + tg + 4]);
                a[mt][3] = fu(As[r + 8][ks * 8 + tg + 4]);
            }
            #pragma unroll
            for (int nt = 0; nt < 8; nt++) {
                int c = wn * 64 + nt * 8 + g;
                unsigned b0 = fu(Bs[ks * 8 + tg    ][c]);
                unsigned b1 = fu(Bs[ks * 8 + tg + 4][c]);
                mma8(acc[0][nt], a[0][0], a[0][1], a[0][2], a[0][3], b0, b1);
                mma8(acc[1][nt], a[1][0], a[1][1], a[1][2], a[1][3], b0, b1);
            }
        }
    }

    // Epilogue: add bias, scatter into [b][h][s][e]
    #pragma unroll
    for (int mt = 0; mt < 2; mt++) {
        int r = row0 + wm * 32 + mt * 16 + g;     // global row over 4096
        int b_ = r >> 11, s = r & 2047;
        #pragma unroll
        for (int nt = 0; nt < 8; nt++) {
            int cg = col0 + wn * 64 + nt * 8 + tg * 2;
            int h = cg >> 6, e = cg & 63;
            float bv0 = bias[cg], bv1 = bias[cg + 1];
            size_t base = ((size_t)b_ * NH + h) * SEQ;
            *(float2*)(Out + (base + s    ) * DHD + e) =
                make_float2(acc[mt][nt][0] + bv0, acc[mt][nt][1] + bv1);
            *(float2*)(Out + (base + s + 8) * DHD + e) =
                make_float2(acc[mt][nt][2] + bv0, acc[mt][nt][3] + bv1);
        }
    }
}

// ---------------------------------------------------------------------------
// Kernel 2: causal flash attention per (b, h, q-tile of 128 rows).
// 8 warps x 16 rows. Q fragments in registers; K/V tiles in smem (tf32);
// P re-laid out through smem for the PV mma. Online softmax in base-2 domain.
// ---------------------------------------------------------------------------
#define KS_STRIDE 68
#define VS_STRIDE 72
#define PS_STRIDE 132
#define ATTN_SMEM ((128*KS_STRIDE + 128*VS_STRIDE + 128*PS_STRIDE) * 4)

__global__ __launch_bounds__(256, 1) void attn_kernel()
{
    extern __shared__ float sm[];
    float* Ks = sm;
    float* Vs = Ks + 128 * KS_STRIDE;
    float* Ps = Vs + 128 * VS_STRIDE;

    const int tid  = threadIdx.x;
    const int warp = tid >> 5, lane = tid & 31;
    const int g = lane >> 2, tg = lane & 3;

    const int idx = blockIdx.x;             // 0..511
    const int qt  = 15 - (idx >> 5);        // heaviest q-tiles scheduled first
    const int bh  = idx & 31;

    const float* Qp = g_Q + (size_t)bh * SEQ * DHD;
    const float* Kp = g_K + (size_t)bh * SEQ * DHD;
    const float* Vp = g_V + (size_t)bh * SEQ * DHD;

    const int qrow = qt * 128 + warp * 16 + g;   // seq-local query row (+8 for 2nd half)
    const int prow = warp * 16 + g;              // row within Ps

    // Q fragments (16 rows x 64 k) resident in registers, tf32-rounded
    unsigned qa[8][4];
    #pragma unroll
    for (int ks = 0; ks < 8; ks++) {
        qa[ks][0] = fu(to_tf32(Qp[(size_t)(qrow    ) * DHD + ks * 8 + tg    ]));
        qa[ks][1] = fu(to_tf32(Qp[(size_t)(qrow + 8) * DHD + ks * 8 + tg    ]));
        qa[ks][2] = fu(to_tf32(Qp[(size_t)(qrow    ) * DHD + ks * 8 + tg + 4]));
        qa[ks][3] = fu(to_tf32(Qp[(size_t)(qrow + 8) * DHD + ks * 8 + tg + 4]));
    }

    const float SCL = 0.125f * 1.4426950408889634f;  // 1/sqrt(64) * log2(e)
    float m0 = -1e30f, m1 = -1e30f, l0 = 0.f, l1 = 0.f;
    float o[8][4];
    #pragma unroll
    for (int nt = 0; nt < 8; nt++)
        #pragma unroll
        for (int c = 0; c < 4; c++) o[nt][c] = 0.f;

    for (int j = 0; j <= qt; j++) {
        __syncthreads();
        const float4* K4 = (const float4*)(Kp + (size_t)j * 128 * DHD);
        const float4* V4 = (const float4*)(Vp + (size_t)j * 128 * DHD);
        #pragma unroll
        for (int u = 0; u < 8; u++) {
            int i = tid + u * 256;          // 2048 float4 per tile
            int r = i >> 4, q = i & 15;
            *(float4*)&Ks[r * KS_STRIDE + q * 4] = tf4(K4[i]);
            *(float4*)&Vs[r * VS_STRIDE + q * 4] = tf4(V4[i]);
        }
        __syncthreads();

        // S = Q K^T  (16 rows x 128 cols per warp)
        float sacc[16][4];
        #pragma unroll
        for (int nt = 0; nt < 16; nt++)
            #pragma unroll
            for (int c = 0; c < 4; c++) sacc[nt][c] = 0.f;

        #pragma unroll
        for (int ks = 0; ks < 8; ks++) {
            #pragma unroll
            for (int nt = 0; nt < 16; nt++) {
                unsigned b0 = fu(Ks[(nt * 8 + g) * KS_STRIDE + ks * 8 + tg    ]);
                unsigned b1 = fu(Ks[(nt * 8 + g) * KS_STRIDE + ks * 8 + tg + 4]);
                mma8(sacc[nt], qa[ks][0], qa[ks][1], qa[ks][2], qa[ks][3], b0, b1);
            }
        }

        // scale (base-2 domain) + causal mask (only diagonal tile needs it)
        const bool diag = (j == qt);
        #pragma unroll
        for (int nt = 0; nt < 16; nt++) {
            #pragma unroll
            for (int c = 0; c < 4; c++) sacc[nt][c] *= SCL;
            if (diag) {
                int kc = j * 128 + nt * 8 + tg * 2;
                if (kc     > qrow    ) sacc[nt][0] = -1e30f;
                if (kc + 1 > qrow    ) sacc[nt][1] = -1e30f;
                if (kc     > qrow + 8) sacc[nt][2] = -1e30f;
                if (kc + 1 > qrow + 8) sacc[nt][3] = -1e30f;
            }
        }

        // row max (local + quad butterfly)
        float rm0 = -1e30f, rm1 = -1e30f;
        #pragma unroll
        for (int nt = 0; nt < 16; nt++) {
            rm0 = fmaxf(rm0, fmaxf(sacc[nt][0], sacc[nt][1]));
            rm1 = fmaxf(rm1, fmaxf(sacc[nt][2], sacc[nt][3]));
        }
        rm0 = fmaxf(rm0, __shfl_xor_sync(0xffffffffu, rm0, 1));
        rm0 = fmaxf(rm0, __shfl_xor_sync(0xffffffffu, rm0, 2));
        rm1 = fmaxf(rm1, __shfl_xor_sync(0xffffffffu, rm1, 1));
        rm1 = fmaxf(rm1, __shfl_xor_sync(0xffffffffu, rm1, 2));

        float mn0 = fmaxf(m0, rm0), mn1 = fmaxf(m1, rm1);
        float al0 = fast_ex2(m0 - mn0), al1 = fast_ex2(m1 - mn1);
        l0 *= al0; l1 *= al1;
        #pragma unroll
        for (int nt = 0; nt < 8; nt++) {
            o[nt][0] *= al0; o[nt][1] *= al0;
            o[nt][2] *= al1; o[nt][3] *= al1;
        }

        // P = exp2(s - m), store tf32 P to smem, accumulate row sums
        float rs0 = 0.f, rs1 = 0.f;
        #pragma unroll
        for (int nt = 0; nt < 16; nt++) {
            float p0 = fast_ex2(sacc[nt][0] - mn0);
            float p1 = fast_ex2(sacc[nt][1] - mn0);
            float p2 = fast_ex2(sacc[nt][2] - mn1);
            float p3 = fast_ex2(sacc[nt][3] - mn1);
            rs0 += p0 + p1; rs1 += p2 + p3;
            *(float2*)&Ps[(prow    ) * PS_STRIDE + nt * 8 + tg * 2] =
                make_float2(to_tf32(p0), to_tf32(p1));
            *(float2*)&Ps[(prow + 8) * PS_STRIDE + nt * 8 + tg * 2] =
                make_float2(to_tf32(p2), to_tf32(p3));
        }
        rs0 += __shfl_xor_sync(0xffffffffu, rs0, 1);
        rs0 += __shfl_xor_sync(0xffffffffu, rs0, 2);
        rs1 += __shfl_xor_sync(0xffffffffu, rs1, 1);
        rs1 += __shfl_xor_sync(0xffffffffu, rs1, 2);
        l0 += rs0; l1 += rs1;
        m0 = mn0;  m1 = mn1;

        __syncwarp();

        // O += P V   (P: 16x128, V: 128x64)
        #pragma unroll
        for (int ks = 0; ks < 16; ks++) {
            unsigned pa0 = fu(Ps[(prow    ) * PS_STRIDE + ks * 8 + tg    ]);
            unsigned pa1 = fu(Ps[(prow + 8) * PS_STRIDE + ks * 8 + tg    ]);
            unsigned pa2 = fu(Ps[(prow    ) * PS_STRIDE + ks * 8 + tg + 4]);
            unsigned pa3 = fu(Ps[(prow + 8) * PS_STRIDE + ks * 8 + tg + 4]);
            #pragma unroll
            for (int nt = 0; nt < 8; nt++) {
                unsigned b0 = fu(Vs[(ks * 8 + tg    ) * VS_STRIDE + nt * 8 + g]);
                unsigned b1 = fu(Vs[(ks * 8 + tg + 4) * VS_STRIDE + nt * 8 + g]);
                mma8(o[nt], pa0, pa1, pa2, pa3, b0, b1);
            }
        }
    }

    // normalize + write Z in [b][s][h*64+e] layout
    float inv0 = 1.f / l0, inv1 = 1.f / l1;
    const int b_ = bh >> 4, h = bh & 15;
    size_t base = ((size_t)b_ * SEQ + qrow) * DM + h * DHD;
    #pragma unroll
    for (int nt = 0; nt < 8; nt++) {
        int e = nt * 8 + tg * 2;
        *(float2*)(g_Z + base + e) =
            make_float2(o[nt][0] * inv0, o[nt][1] * inv0);
        *(float2*)(g_Z + base + (size_t)8 * DM + e) =
            make_float2(o[nt][2] * inv1, o[nt][3] * inv1);
    }
}

// ---------------------------------------------------------------------------
// Kernel 3: output projection. out[4096,1024] = Z[4096,1024] @ Wo[1024,1024] + bO
// ---------------------------------------------------------------------------
__global__ __launch_bounds__(256) void oproj_kernel(
    const float* __restrict__ Wo, const float* __restrict__ bo,
    float* __restrict__ out)
{
    __shared__ float As[128][20];
    __shared__ float Bs[16][136];

    const int tid  = threadIdx.x;
    const int warp = tid >> 5, lane = tid & 31;
    const int g = lane >> 2, tg = lane & 3;
    const int wm = warp >> 1, wn = warp & 1;
    const int row0 = blockIdx.x * 128;
    const int col0 = blockIdx.y * 128;

    float acc[2][8][4];
    #pragma unroll
    for (int i = 0; i < 2; i++)
        #pragma unroll
        for (int j = 0; j < 8; j++)
            #pragma unroll
            for (int k = 0; k < 4; k++) acc[i][j][k] = 0.f;

    for (int k0 = 0; k0 < DM; k0 += 16) {
        __syncthreads();
        #pragma unroll
        for (int u = 0; u < 2; u++) {
            int i = tid + u * 256;
            int r = i >> 2, q = i & 3;
            float4 v = *(const float4*)(g_Z + (size_t)(row0 + r) * DM + k0 + q * 4);
            *(float4*)&As[r][q * 4] = tf4(v);
        }
        #pragma unroll
        for (int u = 0; u < 2; u++) {
            int i = tid + u * 256;
            int k = i >> 5, cq = i & 31;
            float4 v = *(const float4*)(Wo + (size_t)(k0 + k) * DM + col0 + cq * 4);
            *(float4*)&Bs[k][cq * 4] = tf4(v);
        }
        __syncthreads();

        #pragma unroll
        for (int ks = 0; ks < 2; ks++) {
            unsigned a[2][4];
            #pragma unroll
            for (int mt = 0; mt < 2; mt++) {
                int r = wm * 32 + mt * 16 + g;
                a[mt][0] = fu(As[r    ][ks * 8 + tg]);
                a[mt][1] = fu(As[r + 8][ks * 8 + tg]);
                a[mt][2] = fu(As[r    ][ks * 8 + tg + 4]);
                a[mt][3] = fu(As[r + 8][ks * 8 + tg + 4]);
            }
            #pragma unroll
            for (int nt = 0; nt < 8; nt++) {
                int c = wn * 64 + nt * 8 + g;
                unsigned b0 = fu(Bs[ks * 8 + tg    ][c]);
                unsigned b1 = fu(Bs[ks * 8 + tg + 4][c]);
                mma8(acc[0][nt], a[0][0], a[0][1], a[0][2], a[0][3], b0, b1);
                mma8(acc[1][nt], a[1][0], a[1][1], a[1][2], a[1][3], b0, b1);
            }
        }
    }

    #pragma unroll
    for (int mt = 0; mt < 2; mt++) {
        int r = row0 + wm * 32 + mt * 16 + g;
        #pragma unroll
        for (int nt = 0; nt < 8; nt++) {
            int cg = col0 + wn * 64 + nt * 8 + tg * 2;
            float bv0 = bo[cg], bv1 = bo[cg + 1];
            *(float2*)(out + (size_t)(r    ) * DM + cg) =
                make_float2(acc[mt][nt][0] + bv0, acc[mt][nt][1] + bv1);
            *(float2*)(out + (size_t)(r + 8) * DM + cg) =
                make_float2(acc[mt][nt][2] + bv0, acc[mt][nt][3] + bv1);
        }
    }
}

// ---------------------------------------------------------------------------
extern "C" void kernel_launch(void* const* d_in, const int* in_sizes, int n_in,
                              void* d_out, int out_size)
{
    (void)in_sizes; (void)n_in; (void)out_size;
    const float* x  = (const float*)d_in[0];
    const float* Wq = (const float*)d_in[1];
    const float* Wk = (const float*)d_in[2];
    const float* Wv = (const float*)d_in[3];
    const float* Wo = (const float*)d_in[4];
    const float* bq = (const float*)d_in[5];
    const float* bk = (const float*)d_in[6];
    const float* bv = (const float*)d_in[7];
    const float* bo = (const float*)d_in[8];
    float* out = (float*)d_out;

    cudaFuncSetAttribute(attn_kernel,
        cudaFuncAttributeMaxDynamicSharedMemorySize, ATTN_SMEM);

    dim3 g1(32, 8, 3);
    qkv_kernel<<<g1, 256>>>(x, Wq, Wk, Wv, bq, bk, bv);

    attn_kernel<<<512, 256, ATTN_SMEM>>>();

    dim3 g3(32, 8);
    oproj_kernel<<<g3, 256>>>(Wo, bo, out);
}

// round 5
// speedup vs baseline: 1.0830x; 1.0830x over previous
#include <cuda_runtime.h>
#include <cstdint>

#define NB   2
#define SEQ  2048
#define DM   1024
#define NH   16
#define DHD  64

// Scratch (allocation-free rule: __device__ globals)
static __device__ float g_Q[NB*NH*SEQ*DHD];
static __device__ float g_K[NB*NH*SEQ*DHD];
static __device__ float g_V[NB*NH*SEQ*DHD];
static __device__ float g_Z[(size_t)NB*SEQ*DM];

__device__ __forceinline__ float to_tf32(float x){
    float y; asm("cvt.rna.tf32.f32 %0, %1;" : "=f"(y) : "f"(x)); return y;
}
__device__ __forceinline__ float4 tf4(float4 v){
    return make_float4(to_tf32(v.x), to_tf32(v.y), to_tf32(v.z), to_tf32(v.w));
}
__device__ __forceinline__ unsigned fu(float x){ return __float_as_uint(x); }
__device__ __forceinline__ float fast_ex2(float x){
    float y; asm("ex2.approx.f32 %0, %1;" : "=f"(y) : "f"(x)); return y;
}
__device__ __forceinline__ void mma8(float* c,
    unsigned a0, unsigned a1, unsigned a2, unsigned a3,
    unsigned b0, unsigned b1)
{
    asm volatile(
      "mma.sync.aligned.m16n8k8.row.col.f32.tf32.tf32.f32 "
      "{%0,%1,%2,%3},{%4,%5,%6,%7},{%8,%9},{%0,%1,%2,%3};"
      : "+f"(c[0]), "+f"(c[1]), "+f"(c[2]), "+f"(c[3])
      : "r"(a0), "r"(a1), "r"(a2), "r"(a3), "r"(b0), "r"(b1));
}
// ldmatrix x4 on tf32 data (each 8x4 tf32 block == one 8x8 b16 matrix)
__device__ __forceinline__ void ldsm4(unsigned &d0, unsigned &d1, unsigned &d2, unsigned &d3,
                                      const float* p)
{
    unsigned a = (unsigned)__cvta_generic_to_shared(p);
    asm volatile("ldmatrix.sync.aligned.m8n8.x4.shared.b16 {%0,%1,%2,%3}, [%4];"
        : "=r"(d0), "=r"(d1), "=r"(d2), "=r"(d3) : "r"(a));
}

// ---------------------------------------------------------------------------
// GEMM smem geometry (qkv / oproj): BK=32, double buffered.
//   A: [128][36]  row-major (LDSM-friendly; stride 36 -> conflict-free phases)
//   B: [32][136]  row-major (scalar frag LDS; proven conflict-free)
// ---------------------------------------------------------------------------
#define GEMM_SMEM ((2*(128*36) + 2*(32*136)) * 4)   // 71680 B

// ---------------------------------------------------------------------------
// Kernel 1: QKV projection. grid (32, 8, 3).
// ---------------------------------------------------------------------------
__global__ __launch_bounds__(256) void qkv_kernel(
    const float* __restrict__ x,
    const float* __restrict__ Wq, const float* __restrict__ Wk, const float* __restrict__ Wv,
    const float* __restrict__ bq, const float* __restrict__ bk, const float* __restrict__ bv)
{
    extern __shared__ float sm[];
    float* Abuf[2] = { sm,        sm + 4608 };
    float* Bbuf[2] = { sm + 9216, sm + 9216 + 4352 };

    const int tid  = threadIdx.x;
    const int warp = tid >> 5, lane = tid & 31;
    const int g = lane >> 2, tg = lane & 3;
    const int wm = warp >> 1, wn = warp & 1;
    const int row0 = blockIdx.x * 128;
    const int col0 = blockIdx.y * 128;
    const int z = blockIdx.z;

    const float* W    = (z == 0) ? Wq : (z == 1) ? Wk : Wv;
    const float* bias = (z == 0) ? bq : (z == 1) ? bk : bv;
    float* Out        = (z == 0) ? g_Q : (z == 1) ? g_K : g_V;

    // loader coordinates
    const int rA  = tid >> 3;            // +32u rows
    const int kqA = (tid & 7) * 4;       // k offset within stage
    const int kB  = warp;                // +8u k rows
    const int cB  = lane * 4;            // col within tile
    const int ccg = col0 + cB;
    const int bh  = ccg >> 6, be = ccg & 63;   // head / e for W addressing
    // LDSM lane address parts (A fragment)
    const int a_r = ((lane >> 3) & 1) * 8 + (lane & 7);
    const int a_k = ((lane >> 4) & 1) * 4;

    float acc[2][8][4];
    #pragma unroll
    for (int i = 0; i < 2; i++)
        #pragma unroll
        for (int j = 0; j < 8; j++)
            #pragma unroll
            for (int k = 0; k < 4; k++) acc[i][j][k] = 0.f;

    float4 pa[4], pb[4];

    #pragma unroll
    for (int u = 0; u < 4; u++)
        pa[u] = *(const float4*)(x + (size_t)(row0 + rA + 32*u) * DM + kqA);
    #pragma unroll
    for (int u = 0; u < 4; u++)
        pb[u] = *(const float4*)(W + ((size_t)bh * DM + kB + 8*u) * DHD + be);
    #pragma unroll
    for (int u = 0; u < 4; u++)
        *(float4*)(Abuf[0] + (rA + 32*u) * 36 + kqA) = tf4(pa[u]);
    #pragma unroll
    for (int u = 0; u < 4; u++)
        *(float4*)(Bbuf[0] + (kB + 8*u) * 136 + cB) = tf4(pb[u]);
    __syncthreads();

    float* Acur = Abuf[0];  float* Anxt = Abuf[1];
    float* Bcur = Bbuf[0];  float* Bnxt = Bbuf[1];

    for (int s = 0; s < 32; s++) {
        if (s < 31) {
            int k0 = (s + 1) * 32;
            #pragma unroll
            for (int u = 0; u < 4; u++)
                pa[u] = *(const float4*)(x + (size_t)(row0 + rA + 32*u) * DM + k0 + kqA);
            #pragma unroll
            for (int u = 0; u < 4; u++)
                pb[u] = *(const float4*)(W + ((size_t)bh * DM + k0 + kB + 8*u) * DHD + be);
        }
        #pragma unroll
        for (int ks = 0; ks < 4; ks++) {
            unsigned x0,x1,x2,x3, y0,y1,y2,y3;
            ldsm4(x0,x1,x2,x3, Acur + (wm*32      + a_r) * 36 + ks*8 + a_k);
            ldsm4(y0,y1,y2,y3, Acur + (wm*32 + 16 + a_r) * 36 + ks*8 + a_k);
            #pragma unroll
            for (int nt = 0; nt < 8; nt++) {
                int c = wn * 64 + nt * 8 + g;
                unsigned b0 = fu(Bcur[(ks*8 + tg    ) * 136 + c]);
                unsigned b1 = fu(Bcur[(ks*8 + tg + 4) * 136 + c]);
                mma8(acc[0][nt], x0,x1,x2,x3, b0,b1);
                mma8(acc[1][nt], y0,y1,y2,y3, b0,b1);
            }
        }
        if (s < 31) {
            #pragma unroll
            for (int u = 0; u < 4; u++)
                *(float4*)(Anxt + (rA + 32*u) * 36 + kqA) = tf4(pa[u]);
            #pragma unroll
            for (int u = 0; u < 4; u++)
                *(float4*)(Bnxt + (kB + 8*u) * 136 + cB) = tf4(pb[u]);
            __syncthreads();
            float* t;
            t = Acur; Acur = Anxt; Anxt = t;
            t = Bcur; Bcur = Bnxt; Bnxt = t;
        }
    }

    // Epilogue: add bias, scatter into [b][h][s][e]
    #pragma unroll
    for (int mt = 0; mt < 2; mt++) {
        int r = row0 + wm * 32 + mt * 16 + g;
        int b_ = r >> 11, s = r & 2047;
        #pragma unroll
        for (int nt = 0; nt < 8; nt++) {
            int cg = col0 + wn * 64 + nt * 8 + tg * 2;
            int h = cg >> 6, e = cg & 63;
            float bv0 = bias[cg], bv1 = bias[cg + 1];
            size_t base = ((size_t)b_ * NH + h) * SEQ;
            *(float2*)(Out + (base + s    ) * DHD + e) =
                make_float2(acc[mt][nt][0] + bv0, acc[mt][nt][1] + bv1);
            *(float2*)(Out + (base + s + 8) * DHD + e) =
                make_float2(acc[mt][nt][2] + bv0, acc[mt][nt][3] + bv1);
        }
    }
}

// ---------------------------------------------------------------------------
// Kernel 2: causal flash attention per (b, h, q-tile of 128 rows).
// ---------------------------------------------------------------------------
#define KS_STRIDE 68
#define VS_STRIDE 72
#define PS_STRIDE 132
#define ATTN_SMEM ((128*KS_STRIDE + 128*VS_STRIDE + 128*PS_STRIDE) * 4)

__global__ __launch_bounds__(256, 1) void attn_kernel()
{
    extern __shared__ float sm[];
    float* Ks = sm;
    float* Vs = Ks + 128 * KS_STRIDE;
    float* Ps = Vs + 128 * VS_STRIDE;

    const int tid  = threadIdx.x;
    const int warp = tid >> 5, lane = tid & 31;
    const int g = lane >> 2, tg = lane & 3;
    // LDSM lane address parts
    const int a_r = ((lane >> 3) & 1) * 8 + (lane & 7);   // A-frag row part
    const int a_k = ((lane >> 4) & 1) * 4;                // A-frag k part
    const int k_c = ((lane >> 4) & 1) * 8 + (lane & 7);   // B-frag col part
    const int k_k = ((lane >> 3) & 1) * 4;                // B-frag k part

    const int idx = blockIdx.x;             // 0..511
    const int qt  = 15 - (idx >> 5);        // heaviest q-tiles scheduled first
    const int bh  = idx & 31;

    const float* Qp = g_Q + (size_t)bh * SEQ * DHD;
    const float* Kp = g_K + (size_t)bh * SEQ * DHD;
    const float* Vp = g_V + (size_t)bh * SEQ * DHD;

    const int qrow = qt * 128 + warp * 16 + g;
    const int prow = warp * 16 + g;

    // Q fragments resident in registers (tf32-rounded)
    unsigned qa[8][4];
    #pragma unroll
    for (int ks = 0; ks < 8; ks++) {
        qa[ks][0] = fu(to_tf32(Qp[(size_t)(qrow    ) * DHD + ks * 8 + tg    ]));
        qa[ks][1] = fu(to_tf32(Qp[(size_t)(qrow + 8) * DHD + ks * 8 + tg    ]));
        qa[ks][2] = fu(to_tf32(Qp[(size_t)(qrow    ) * DHD + ks * 8 + tg + 4]));
        qa[ks][3] = fu(to_tf32(Qp[(size_t)(qrow + 8) * DHD + ks * 8 + tg + 4]));
    }

    const float SCL = 0.125f * 1.4426950408889634f;  // 1/sqrt(64) * log2(e)
    float m0 = -1e30f, m1 = -1e30f, l0 = 0.f, l1 = 0.f;
    float o[8][4];
    #pragma unroll
    for (int nt = 0; nt < 8; nt++)
        #pragma unroll
        for (int c = 0; c < 4; c++) o[nt][c] = 0.f;

    for (int j = 0; j <= qt; j++) {
        __syncthreads();
        const float4* K4 = (const float4*)(Kp + (size_t)j * 128 * DHD);
        const float4* V4 = (const float4*)(Vp + (size_t)j * 128 * DHD);
        #pragma unroll
        for (int u = 0; u < 8; u++) {
            int i = tid + u * 256;
            int r = i >> 4, q = i & 15;
            *(float4*)&Ks[r * KS_STRIDE + q * 4] = tf4(K4[i]);
            *(float4*)&Vs[r * VS_STRIDE + q * 4] = tf4(V4[i]);
        }
        __syncthreads();

        // S = Q K^T  (16 rows x 128 cols per warp), K-frags via ldmatrix.x4
        float sacc[16][4];
        #pragma unroll
        for (int nt = 0; nt < 16; nt++)
            #pragma unroll
            for (int c = 0; c < 4; c++) sacc[nt][c] = 0.f;

        #pragma unroll
        for (int ntp = 0; ntp < 8; ntp++) {
            #pragma unroll
            for (int ks = 0; ks < 8; ks++) {
                unsigned b0,b1,b2,b3;
                ldsm4(b0,b1,b2,b3, Ks + (ntp*16 + k_c) * KS_STRIDE + ks*8 + k_k);
                mma8(sacc[2*ntp    ], qa[ks][0],qa[ks][1],qa[ks][2],qa[ks][3], b0,b1);
                mma8(sacc[2*ntp + 1], qa[ks][0],qa[ks][1],qa[ks][2],qa[ks][3], b2,b3);
            }
        }

        // scale (base-2 domain) + causal mask (only diagonal tile)
        const bool diag = (j == qt);
        #pragma unroll
        for (int nt = 0; nt < 16; nt++) {
            #pragma unroll
            for (int c = 0; c < 4; c++) sacc[nt][c] *= SCL;
            if (diag) {
                int kc = j * 128 + nt * 8 + tg * 2;
                if (kc     > qrow    ) sacc[nt][0] = -1e30f;
                if (kc + 1 > qrow    ) sacc[nt][1] = -1e30f;
                if (kc     > qrow + 8) sacc[nt][2] = -1e30f;
                if (kc + 1 > qrow + 8) sacc[nt][3] = -1e30f;
            }
        }

        // row max (local + quad butterfly)
        float rm0 = -1e30f, rm1 = -1e30f;
        #pragma unroll
        for (int nt = 0; nt < 16; nt++) {
            rm0 = fmaxf(rm0, fmaxf(sacc[nt][0], sacc[nt][1]));
            rm1 = fmaxf(rm1, fmaxf(sacc[nt][2], sacc[nt][3]));
        }
        rm0 = fmaxf(rm0, __shfl_xor_sync(0xffffffffu, rm0, 1));
        rm0 = fmaxf(rm0, __shfl_xor_sync(0xffffffffu, rm0, 2));
        rm1 = fmaxf(rm1, __shfl_xor_sync(0xffffffffu, rm1, 1));
        rm1 = fmaxf(rm1, __shfl_xor_sync(0xffffffffu, rm1, 2));

        float mn0 = fmaxf(m0, rm0), mn1 = fmaxf(m1, rm1);
        float al0 = fast_ex2(m0 - mn0), al1 = fast_ex2(m1 - mn1);
        l0 *= al0; l1 *= al1;
        #pragma unroll
        for (int nt = 0; nt < 8; nt++) {
            o[nt][0] *= al0; o[nt][1] *= al0;
            o[nt][2] *= al1; o[nt][3] *= al1;
        }

        // P = exp2(s - m), store tf32 P to smem, accumulate row sums
        float rs0 = 0.f, rs1 = 0.f;
        #pragma unroll
        for (int nt = 0; nt < 16; nt++) {
            float p0 = fast_ex2(sacc[nt][0] - mn0);
            float p1 = fast_ex2(sacc[nt][1] - mn0);
            float p2 = fast_ex2(sacc[nt][2] - mn1);
            float p3 = fast_ex2(sacc[nt][3] - mn1);
            rs0 += p0 + p1; rs1 += p2 + p3;
            *(float2*)&Ps[(prow    ) * PS_STRIDE + nt * 8 + tg * 2] =
                make_float2(to_tf32(p0), to_tf32(p1));
            *(float2*)&Ps[(prow + 8) * PS_STRIDE + nt * 8 + tg * 2] =
                make_float2(to_tf32(p2), to_tf32(p3));
        }
        rs0 += __shfl_xor_sync(0xffffffffu, rs0, 1);
        rs0 += __shfl_xor_sync(0xffffffffu, rs0, 2);
        rs1 += __shfl_xor_sync(0xffffffffu, rs1, 1);
        rs1 += __shfl_xor_sync(0xffffffffu, rs1, 2);
        l0 += rs0; l1 += rs1;
        m0 = mn0;  m1 = mn1;

        __syncwarp();

        // O += P V : P-frags via ldmatrix.x4, V scalar (conflict-free layout)
        #pragma unroll
        for (int ks = 0; ks < 16; ks++) {
            unsigned p0,p1,p2,p3;
            ldsm4(p0,p1,p2,p3, Ps + (warp*16 + a_r) * PS_STRIDE + ks*8 + a_k);
            #pragma unroll
            for (int nt = 0; nt < 8; nt++) {
                unsigned b0 = fu(Vs[(ks*8 + tg    ) * VS_STRIDE + nt*8 + g]);
                unsigned b1 = fu(Vs[(ks*8 + tg + 4) * VS_STRIDE + nt*8 + g]);
                mma8(o[nt], p0,p1,p2,p3, b0,b1);
            }
        }
    }

    // normalize + write Z in [b][s][h*64+e] layout
    float inv0 = 1.f / l0, inv1 = 1.f / l1;
    const int b_ = bh >> 4, h = bh & 15;
    size_t base = ((size_t)b_ * SEQ + qrow) * DM + h * DHD;
    #pragma unroll
    for (int nt = 0; nt < 8; nt++) {
        int e = nt * 8 + tg * 2;
        *(float2*)(g_Z + base + e) =
            make_float2(o[nt][0] * inv0, o[nt][1] * inv0);
        *(float2*)(g_Z + base + (size_t)8 * DM + e) =
            make_float2(o[nt][2] * inv1, o[nt][3] * inv1);
    }
}

// ---------------------------------------------------------------------------
// Kernel 3: output projection (same pipelined structure as qkv).
// ---------------------------------------------------------------------------
__global__ __launch_bounds__(256) void oproj_kernel(
    const float* __restrict__ Wo, const float* __restrict__ bo,
    float* __restrict__ out)
{
    extern __shared__ float sm[];
    float* Abuf[2] = { sm,        sm + 4608 };
    float* Bbuf[2] = { sm + 9216, sm + 9216 + 4352 };

    const int tid  = threadIdx.x;
    const int warp = tid >> 5, lane = tid & 31;
    const int g = lane >> 2, tg = lane & 3;
    const int wm = warp >> 1, wn = warp & 1;
    const int row0 = blockIdx.x * 128;
    const int col0 = blockIdx.y * 128;

    const int rA  = tid >> 3;
    const int kqA = (tid & 7) * 4;
    const int kB  = warp;
    const int cB  = lane * 4;
    const int a_r = ((lane >> 3) & 1) * 8 + (lane & 7);
    const int a_k = ((lane >> 4) & 1) * 4;

    float acc[2][8][4];
    #pragma unroll
    for (int i = 0; i < 2; i++)
        #pragma unroll
        for (int j = 0; j < 8; j++)
            #pragma unroll
            for (int k = 0; k < 4; k++) acc[i][j][k] = 0.f;

    float4 pa[4], pb[4];
    #pragma unroll
    for (int u = 0; u < 4; u++)
        pa[u] = *(const float4*)(g_Z + (size_t)(row0 + rA + 32*u) * DM + kqA);
    #pragma unroll
    for (int u = 0; u < 4; u++)
        pb[u] = *(const float4*)(Wo + (size_t)(kB + 8*u) * DM + col0 + cB);
    #pragma unroll
    for (int u = 0; u < 4; u++)
        *(float4*)(Abuf[0] + (rA + 32*u) * 36 + kqA) = tf4(pa[u]);
    #pragma unroll
    for (int u = 0; u < 4; u++)
        *(float4*)(Bbuf[0] + (kB + 8*u) * 136 + cB) = tf4(pb[u]);
    __syncthreads();

    float* Acur = Abuf[0];  float* Anxt = Abuf[1];
    float* Bcur = Bbuf[0];  float* Bnxt = Bbuf[1];

    for (int s = 0; s < 32; s++) {
        if (s < 31) {
            int k0 = (s + 1) * 32;
            #pragma unroll
            for (int u = 0; u < 4; u++)
                pa[u] = *(const float4*)(g_Z + (size_t)(row0 + rA + 32*u) * DM + k0 + kqA);
            #pragma unroll
            for (int u = 0; u < 4; u++)
                pb[u] = *(const float4*)(Wo + (size_t)(k0 + kB + 8*u) * DM + col0 + cB);
        }
        #pragma unroll
        for (int ks = 0; ks < 4; ks++) {
            unsigned x0,x1,x2,x3, y0,y1,y2,y3;
            ldsm4(x0,x1,x2,x3, Acur + (wm*32      + a_r) * 36 + ks*8 + a_k);
            ldsm4(y0,y1,y2,y3, Acur + (wm*32 + 16 + a_r) * 36 + ks*8 + a_k);
            #pragma unroll
            for (int nt = 0; nt < 8; nt++) {
                int c = wn * 64 + nt * 8 + g;
                unsigned b0 = fu(Bcur[(ks*8 + tg    ) * 136 + c]);
                unsigned b1 = fu(Bcur[(ks*8 + tg + 4) * 136 + c]);
                mma8(acc[0][nt], x0,x1,x2,x3, b0,b1);
                mma8(acc[1][nt], y0,y1,y2,y3, b0,b1);
            }
        }
        if (s < 31) {
            #pragma unroll
            for (int u = 0; u < 4; u++)
                *(float4*)(Anxt + (rA + 32*u) * 36 + kqA) = tf4(pa[u]);
            #pragma unroll
            for (int u = 0; u < 4; u++)
                *(float4*)(Bnxt + (kB + 8*u) * 136 + cB) = tf4(pb[u]);
            __syncthreads();
            float* t;
            t = Acur; Acur = Anxt; Anxt = t;
            t = Bcur; Bcur = Bnxt; Bnxt = t;
        }
    }

    #pragma unroll
    for (int mt = 0; mt < 2; mt++) {
        int r = row0 + wm * 32 + mt * 16 + g;
        #pragma unroll
        for (int nt = 0; nt < 8; nt++) {
            int cg = col0 + wn * 64 + nt * 8 + tg * 2;
            float bv0 = bo[cg], bv1 = bo[cg + 1];
            *(float2*)(out + (size_t)(r    ) * DM + cg) =
                make_float2(acc[mt][nt][0] + bv0, acc[mt][nt][1] + bv1);
            *(float2*)(out + (size_t)(r + 8) * DM + cg) =
                make_float2(acc[mt][nt][2] + bv0, acc[mt][nt][3] + bv1);
        }
    }
}

// ---------------------------------------------------------------------------
extern "C" void kernel_launch(void* const* d_in, const int* in_sizes, int n_in,
                              void* d_out, int out_size)
{
    (void)in_sizes; (void)n_in; (void)out_size;
    const float* x  = (const float*)d_in[0];
    const float* Wq = (const float*)d_in[1];
    const float* Wk = (const float*)d_in[2];
    const float* Wv = (const float*)d_in[3];
    const float* Wo = (const float*)d_in[4];
    const float* bq = (const float*)d_in[5];
    const float* bk = (const float*)d_in[6];
    const float* bv = (const float*)d_in[7];
    const float* bo = (const float*)d_in[8];
    float* out = (float*)d_out;

    static bool attr_done = false;
    if (!attr_done) {
        cudaFuncSetAttribute(qkv_kernel,
            cudaFuncAttributeMaxDynamicSharedMemorySize, GEMM_SMEM);
        cudaFuncSetAttribute(attn_kernel,
            cudaFuncAttributeMaxDynamicSharedMemorySize, ATTN_SMEM);
        cudaFuncSetAttribute(oproj_kernel,
            cudaFuncAttributeMaxDynamicSharedMemorySize, GEMM_SMEM);
        attr_done = true;
    }

    dim3 g1(32, 8, 3);
    qkv_kernel<<<g1, 256, GEMM_SMEM>>>(x, Wq, Wk, Wv, bq, bk, bv);

    attn_kernel<<<512, 256, ATTN_SMEM>>>();

    dim3 g3(32, 8);
    oproj_kernel<<<g3, 256, GEMM_SMEM>>>(Wo, bo, out);
}